// round 16
// baseline (speedup 1.0000x reference)
#include <cuda_runtime.h>
#include <cuda_fp16.h>
#include <cstdint>

#define NB 32
#define NC 512
#define NL 512
#define NH 8
#define NDK 64
#define LC (512 * 512)

// Scratch (device globals). All intermediates fp16.
__device__ __half g_tq[NB * NC * NL];    // dwconv outputs, (b, l, c)
__device__ __half g_tk[NB * NC * NL];
__device__ __half g_tv[NB * NC * NL];
__device__ __half g_q[NB * NC * NL];     // (b, l, c)
__device__ __half g_k[NB * NC * NL];
__device__ __half g_v[NB * NC * NL];
__device__ __half g_o[NB * NC * NL];     // attention output (b, c, i)
__device__ __half g_whq[NC * NC];        // fp16 weights
__device__ __half g_whk[NC * NC];
__device__ __half g_whv[NC * NC];
__device__ __half g_whp[NC * NC];
__device__ float g_post[NC * NL];        // pos_bias transposed to (C, L)

__device__ __forceinline__ uint32_t pack_h2(float lo, float hi) {
    __half2 h = __floats2half2_rn(lo, hi);
    return *(uint32_t*)&h;
}

__device__ __forceinline__ void mma_f16(float* d, const uint32_t* a, const uint32_t* b) {
    asm volatile(
        "mma.sync.aligned.m16n8k16.row.col.f32.f16.f16.f32 "
        "{%0,%1,%2,%3}, {%4,%5,%6,%7}, {%8,%9}, {%0,%1,%2,%3};"
        : "+f"(d[0]), "+f"(d[1]), "+f"(d[2]), "+f"(d[3])
        : "r"(a[0]), "r"(a[1]), "r"(a[2]), "r"(a[3]), "r"(b[0]), "r"(b[1]));
}

#define LDMATRIX_X4(r0, r1, r2, r3, addr) \
    asm volatile("ldmatrix.sync.aligned.m8n8.x4.shared.b16 {%0,%1,%2,%3}, [%4];" \
        : "=r"(r0), "=r"(r1), "=r"(r2), "=r"(r3) : "r"(addr))
#define LDMATRIX_X2(r0, r1, addr) \
    asm volatile("ldmatrix.sync.aligned.m8n8.x2.shared.b16 {%0,%1}, [%2];" \
        : "=r"(r0), "=r"(r1) : "r"(addr))
#define LDMATRIX_X4_TRANS(r0, r1, r2, r3, addr) \
    asm volatile("ldmatrix.sync.aligned.m8n8.x4.trans.shared.b16 {%0,%1,%2,%3}, [%4];" \
        : "=r"(r0), "=r"(r1), "=r"(r2), "=r"(r3) : "r"(addr))

__device__ __forceinline__ uint32_t smem_to_u32(const void* p) {
    uint32_t a;
    asm("{ .reg .u64 t; cvta.to.shared.u64 t, %1; cvt.u32.u64 %0, t; }"
        : "=r"(a) : "l"(p));
    return a;
}

#define CP_ASYNC_16(dst, src) \
    asm volatile("cp.async.cg.shared.global [%0], [%1], 16;" \
        :: "r"(dst), "l"(src) : "memory")
#define CP_COMMIT() asm volatile("cp.async.commit_group;" ::: "memory")
#define CP_WAIT_0() asm volatile("cp.async.wait_group 0;" ::: "memory")
#define CP_WAIT_1() asm volatile("cp.async.wait_group 1;" ::: "memory")

// ===========================================================================
// Prep kernel (ONE launch): blocks 0..255 transpose pos_bias (L,C)->(C,L);
// blocks 256..767 convert the 4 weight matrices fp32->fp16.
// ===========================================================================
__global__ __launch_bounds__(256) void prep_kernel(
    const float* __restrict__ pos, float* __restrict__ posT,
    const float* w0, const float* w1, const float* w2, const float* w3,
    __half* o0, __half* o1, __half* o2, __half* o3) {
    const int bid = blockIdx.x;
    const int tid = threadIdx.x;
    if (bid < 256) {
        __shared__ float tile[32][33];
        const int c0 = (bid & 15) * 32;
        const int l0 = (bid >> 4) * 32;
        const int tx = tid & 31;
        const int ty = tid >> 5;
#pragma unroll
        for (int r = 0; r < 4; r++)
            tile[ty + r * 8][tx] = pos[(size_t)(l0 + ty + r * 8) * NC + c0 + tx];
        __syncthreads();
#pragma unroll
        for (int r = 0; r < 4; r++)
            posT[(size_t)(c0 + ty + r * 8) * NL + l0 + tx] = tile[tx][ty + r * 8];
    } else {
        const int cb = bid - 256;
        const float* ws[4] = {w0, w1, w2, w3};
        __half* os[4] = {o0, o1, o2, o3};
        const float* w = ws[cb >> 7];
        __half* o = os[cb >> 7];
        const int i = ((cb & 127) * 256 + tid) * 8;
        float4 a = *(const float4*)&w[i];
        float4 b = *(const float4*)&w[i + 4];
        uint4 p;
        p.x = pack_h2(a.x, a.y); p.y = pack_h2(a.z, a.w);
        p.z = pack_h2(b.x, b.y); p.w = pack_h2(b.z, b.w);
        *(uint4*)&o[i] = p;
    }
}

// ===========================================================================
// Merged depthwise conv (q,k,v). fp16 output y[iz][b, l, c].
// ===========================================================================
#define DST 137
__global__ __launch_bounds__(256) void dwconv_merged_kernel(
    const float* x0, const float* x1, const float* x2,
    const float* __restrict__ posT,
    const float* w0, const float* w1, const float* w2,
    const float* b0, const float* b1, const float* b2,
    __half* y0, __half* y1, __half* y2) {
    __shared__ float sx[32 * DST];
    const int tid = threadIdx.x;
    const int c0 = blockIdx.x * 32;
    const int l0 = blockIdx.y * 128;
    const int iz = blockIdx.z >> 5;
    const int b = blockIdx.z & 31;
    const float* xin[3] = {x0, x1, x2};
    const float* win3[3] = {w0, w1, w2};
    const float* bin[3] = {b0, b1, b2};
    __half* yout[3] = {y0, y1, y2};
    const float* x = xin[iz];
    const float* w = win3[iz];
    const float* bias = bin[iz];
    __half* y = yout[iz];
    const int add_pos = (iz < 2);

    {
        const int lr = tid >> 3;
        const int tj = tid & 7;
        const float* xrow = x + ((size_t)b * NC + c0 + lr) * NL;
        const float* prow = posT + (size_t)(c0 + lr) * NL;
        float* sd = &sx[lr * DST];
#pragma unroll
        for (int jj = 0; jj < 5; jj++) {
            const int j = tj + jj * 8;
            if (j < 34) {
                const int l = l0 - 4 + 4 * j;
                float4 v = {0.f, 0.f, 0.f, 0.f};
                if (l >= 0 && l <= 508) {
                    v = *(const float4*)&xrow[l];
                    if (add_pos) {
                        float4 p = *(const float4*)&prow[l];
                        v.x += p.x; v.y += p.y; v.z += p.z; v.w += p.w;
                    }
                }
                sd[4 * j + 0] = v.x; sd[4 * j + 1] = v.y;
                sd[4 * j + 2] = v.z; sd[4 * j + 3] = v.w;
            }
        }
    }
    __syncthreads();

    const int cc = tid & 31;
    const int o0 = (tid >> 5) * 16;
    float wt[7];
#pragma unroll
    for (int t = 0; t < 7; t++) wt[t] = w[(c0 + cc) * 7 + t];
    const float bs = bias[c0 + cc];
    const float* xr = &sx[cc * DST];
    float winv[7];
#pragma unroll
    for (int t = 0; t < 6; t++) winv[t] = xr[o0 + 1 + t];
    __half* yb = y + (size_t)b * LC + c0 + cc;
#pragma unroll
    for (int r = 0; r < 16; r++) {
        winv[6] = xr[o0 + r + 7];
        float acc = bs;
#pragma unroll
        for (int t = 0; t < 7; t++) acc += winv[t] * wt[t];
        yb[(size_t)(l0 + o0 + r) * NC] = __float2half_rn(acc);
#pragma unroll
        for (int t = 0; t < 6; t++) winv[t] = winv[t + 1];
    }
}

// ===========================================================================
// Batched GEMM (fp16 m16n8k16): Y = A*W^T + bias.
// 128 threads (4 warps, 2m x 2n), CTA tile 128x64, BK=32, 3-stage cp.async.
// smem 46KB/CTA -> 4 CTAs/SM: four independent barrier domains fill each
// other's sync bubbles. Accumulation order identical to R15 (bit-exact).
// ===========================================================================
#define PKH2 40
#define AST (128 * PKH2)            // A halves per stage
#define BST (64 * PKH2)             // B halves per stage
#define STG (AST + BST)
#define GEMM_SMEM (3 * STG * 2)     // 46080 bytes
template <int OUT16>
__global__ __launch_bounds__(128, 4) void gemm_mma_kernel(
    const __half* A0, const __half* A1, const __half* A2,
    const __half* W0, const __half* W1, const __half* W2,
    const float* bi0, const float* bi1, const float* bi2,
    void* Y0, void* Y1, void* Y2) {
    extern __shared__ __align__(16) __half gsm[];  // [3][STG]: A then B

    const int tid = threadIdx.x;
    const int lane = tid & 31;
    const int g = lane >> 2;
    const int tg = lane & 3;
    const int wm = (tid >> 5) >> 1;   // 0..1
    const int wn = (tid >> 5) & 1;    // 0..1
    const int n0 = blockIdx.x * 64;
    const int m0 = blockIdx.y * 128;
    const int grp = blockIdx.z >> 5;
    const int zb = blockIdx.z & 31;
    const __half* Aarr[3] = {A0, A1, A2};
    const __half* Warr[3] = {W0, W1, W2};
    const float* barr[3] = {bi0, bi1, bi2};
    void* Yarr[3] = {Y0, Y1, Y2};
    const __half* Ab = Aarr[grp] + (size_t)zb * LC;
    const __half* W = Warr[grp];
    const float* bias = barr[grp];

    // staging: A row = tid (0..127), 64B per chunk (4 cp.async);
    //          B row = tid>>1 (0..63), half hh (tid&1), 32B (2 cp.async)
    const __half* Asrc = Ab + (size_t)(m0 + tid) * 512;
    const __half* Bsrc = W + (size_t)(n0 + (tid >> 1)) * 512 + (tid & 1) * 16;
    const uint32_t sm0 = smem_to_u32(gsm);
    const uint32_t aBase = sm0 + (uint32_t)(tid * PKH2) * 2;
    const uint32_t bBase = sm0 + (uint32_t)(AST + (tid >> 1) * PKH2 + (tid & 1) * 16) * 2;

    const int l15 = lane & 15;
    const uint32_t aln = (uint32_t)(l15 * PKH2 + (lane >> 4) * 8);
    const uint32_t bln = (uint32_t)((l15 & 7) * PKH2 + (l15 >> 3) * 8);

    float acc[4][4][4];
#pragma unroll
    for (int mi = 0; mi < 4; mi++)
#pragma unroll
        for (int ni = 0; ni < 4; ni++)
#pragma unroll
            for (int r = 0; r < 4; r++) acc[mi][ni][r] = 0.f;

    // prologue: chunks 0, 1 into stages 0, 1
#pragma unroll
    for (int pc = 0; pc < 2; pc++) {
        const uint32_t so = (uint32_t)(pc * STG * 2);
#pragma unroll
        for (int u = 0; u < 4; u++)
            CP_ASYNC_16(aBase + so + u * 16, Asrc + pc * 32 + u * 8);
#pragma unroll
        for (int u = 0; u < 2; u++)
            CP_ASYNC_16(bBase + so + u * 16, Bsrc + pc * 32 + u * 8);
        CP_COMMIT();
    }

    for (int kc = 0; kc < 16; kc++) {
        CP_WAIT_1();
        __syncthreads();
        if (kc < 14) {
            const int s = (kc + 2) % 3;
            const uint32_t so = (uint32_t)(s * STG * 2);
#pragma unroll
            for (int u = 0; u < 4; u++)
                CP_ASYNC_16(aBase + so + u * 16, Asrc + (kc + 2) * 32 + u * 8);
#pragma unroll
            for (int u = 0; u < 2; u++)
                CP_ASYNC_16(bBase + so + u * 16, Bsrc + (kc + 2) * 32 + u * 8);
        }
        CP_COMMIT();

        const int cur = kc % 3;
        const uint32_t aCur = sm0 + (uint32_t)(cur * STG) * 2;
        const uint32_t bCur = sm0 + (uint32_t)(cur * STG + AST) * 2;
#pragma unroll
        for (int s = 0; s < 2; s++) {
            uint32_t af[4][4];
#pragma unroll
            for (int mi = 0; mi < 4; mi++) {
                const uint32_t addr = aCur +
                    2u * (uint32_t)((wm * 64 + mi * 16) * PKH2 + s * 16 + aln);
                LDMATRIX_X4(af[mi][0], af[mi][1], af[mi][2], af[mi][3], addr);
            }
            uint32_t bf[4][2];
#pragma unroll
            for (int ni = 0; ni < 4; ni++) {
                const uint32_t addr = bCur +
                    2u * (uint32_t)((wn * 32 + ni * 8) * PKH2 + s * 16 + bln);
                LDMATRIX_X2(bf[ni][0], bf[ni][1], addr);
            }
#pragma unroll
            for (int mi = 0; mi < 4; mi++)
#pragma unroll
                for (int ni = 0; ni < 4; ni++)
                    mma_f16(acc[mi][ni], af[mi], bf[ni]);
        }
    }

#pragma unroll
    for (int mi = 0; mi < 4; mi++) {
        const int m = m0 + wm * 64 + mi * 16 + g;
#pragma unroll
        for (int ni = 0; ni < 4; ni++) {
            const int n = n0 + wn * 32 + ni * 8 + 2 * tg;
            const float bn0 = bias[n], bn1 = bias[n + 1];
            if (OUT16) {
                __half* Yb = (__half*)Yarr[grp] + (size_t)zb * LC;
                *(uint32_t*)&Yb[(size_t)m * 512 + n] =
                    pack_h2(acc[mi][ni][0] + bn0, acc[mi][ni][1] + bn1);
                *(uint32_t*)&Yb[(size_t)(m + 8) * 512 + n] =
                    pack_h2(acc[mi][ni][2] + bn0, acc[mi][ni][3] + bn1);
            } else {
                float* Yb = (float*)Yarr[grp] + (size_t)zb * LC;
                float2 o0 = {acc[mi][ni][0] + bn0, acc[mi][ni][1] + bn1};
                float2 o1 = {acc[mi][ni][2] + bn0, acc[mi][ni][3] + bn1};
                *(float2*)&Yb[(size_t)m * 512 + n] = o0;
                *(float2*)&Yb[(size_t)(m + 8) * 512 + n] = o1;
            }
        }
    }
}

// ===========================================================================
// Flash attention (fp16 m16n8k16), 128-i CTA, 256 thr = 8 warps.
// [R15 proven-best config — unchanged]
// ===========================================================================
#define QSH 72
#define KH_OFF (128 * QSH)
#define VH_OFF (KH_OFF + 2 * 64 * QSH)
#define KVT (64 * QSH)
#define ATTN_SMEM ((VH_OFF + 2 * 64 * QSH) * 2)
__global__ __launch_bounds__(256) void attn_mma_kernel(
    const __half* __restrict__ Q, const __half* __restrict__ K,
    const __half* __restrict__ V, __half* __restrict__ O) {
    extern __shared__ __align__(16) char smc[];
    __half* sh = (__half*)smc;
    float* fs = (float*)smc;
    const uint32_t sbase = smem_to_u32(smc);

    const int tid = threadIdx.x;
    const int w = tid >> 5;
    const int lane = tid & 31;
    const int g = lane >> 2;
    const int tg = lane & 3;
    const int it = w >> 2;
    const int wq = w & 3;
    const int b = blockIdx.z;
    const int h = blockIdx.y;
    const int i0 = blockIdx.x * 128;

    const __half* Qb = Q + (size_t)b * LC + h * 64;
    const __half* Kb = K + (size_t)b * LC + h * 64;
    const __half* Vb = V + (size_t)b * LC + h * 64;

    const int krow = tid >> 2;
    const int kq = tid & 3;
    const __half* Ksrc = Kb + (size_t)krow * 512 + kq * 16;
    const __half* Vsrc = Vb + (size_t)krow * 512 + kq * 16;
    const uint32_t kBase = sbase + (uint32_t)(KH_OFF + krow * QSH + kq * 16) * 2;
    const uint32_t vBase = sbase + (uint32_t)(VH_OFF + krow * QSH + kq * 16) * 2;

    CP_ASYNC_16(kBase, Ksrc);
    CP_ASYNC_16(kBase + 16, Ksrc + 8);
    CP_ASYNC_16(vBase, Vsrc);
    CP_ASYNC_16(vBase + 16, Vsrc + 8);
    CP_COMMIT();

    {
        const __half2 sc = __half2half2(__float2half_rn(0.125f));
        const int row = tid >> 1;
        const int half_ = tid & 1;
        const __half* src = Qb + (size_t)(i0 + row) * 512 + half_ * 32;
        __half* qd = sh + row * QSH + half_ * 32;
#pragma unroll
        for (int u = 0; u < 4; u++) {
            uint4 v = *(const uint4*)&src[u * 8];
            __half2* h2 = (__half2*)&v;
            h2[0] = __hmul2(h2[0], sc);
            h2[1] = __hmul2(h2[1], sc);
            h2[2] = __hmul2(h2[2], sc);
            h2[3] = __hmul2(h2[3], sc);
            *(uint4*)&qd[u * 8] = v;
        }
    }
    __syncthreads();

    uint32_t qa[4][4];
    {
        const __half* qrow = sh + (it * 64 + wq * 16 + g) * QSH + 2 * tg;
#pragma unroll
        for (int k0 = 0; k0 < 4; k0++) {
            const __half* qp = qrow + k0 * 16;
            qa[k0][0] = *(const uint32_t*)&qp[0];
            qa[k0][1] = *(const uint32_t*)&qp[8 * QSH];
            qa[k0][2] = *(const uint32_t*)&qp[8];
            qa[k0][3] = *(const uint32_t*)&qp[8 * QSH + 8];
        }
    }

    float m_run0 = -1e30f, m_run1 = -1e30f, l_run0 = 0.f, l_run1 = 0.f;
    float oacc[8][4];
#pragma unroll
    for (int nt = 0; nt < 8; nt++)
#pragma unroll
        for (int r = 0; r < 4; r++) oacc[nt][r] = 0.f;

    const uint32_t vlane = (uint32_t)(((lane & 7) + ((lane >> 3) & 1) * 8) * QSH
                                      + ((lane >> 4) & 1) * 8);
    const int l15 = lane & 15;
    const uint32_t kln = (uint32_t)((l15 & 7) * QSH + (l15 >> 3) * 8 + (lane >> 4) * 16);

    for (int jt = 0; jt < 8; jt++) {
        const int cur = jt & 1;
        CP_WAIT_0();
        __syncthreads();
        if (jt < 7) {
            const int nxt = (jt + 1) & 1;
            const __half* ks = Ksrc + (size_t)(jt + 1) * 64 * 512;
            const __half* vs = Vsrc + (size_t)(jt + 1) * 64 * 512;
            CP_ASYNC_16(kBase + (uint32_t)(nxt * KVT) * 2, ks);
            CP_ASYNC_16(kBase + (uint32_t)(nxt * KVT) * 2 + 16, ks + 8);
            CP_ASYNC_16(vBase + (uint32_t)(nxt * KVT) * 2, vs);
            CP_ASYNC_16(vBase + (uint32_t)(nxt * KVT) * 2 + 16, vs + 8);
        }
        CP_COMMIT();

        const uint32_t kTile = sbase + 2u * (uint32_t)(KH_OFF + cur * KVT);

        float sacc[8][4];
#pragma unroll
        for (int nt = 0; nt < 8; nt++)
#pragma unroll
            for (int r = 0; r < 4; r++) sacc[nt][r] = 0.f;
#pragma unroll
        for (int p = 0; p < 2; p++) {
#pragma unroll
            for (int nt = 0; nt < 8; nt++) {
                const uint32_t addr = kTile +
                    2u * (uint32_t)((nt * 8) * QSH + p * 32 + kln);
                uint32_t r0, r1, r2, r3;
                LDMATRIX_X4(r0, r1, r2, r3, addr);
                uint32_t b0[2] = {r0, r1};
                uint32_t b1[2] = {r2, r3};
                mma_f16(sacc[nt], qa[2 * p], b0);
                mma_f16(sacc[nt], qa[2 * p + 1], b1);
            }
        }

        float mx0 = -1e30f, mx1 = -1e30f;
#pragma unroll
        for (int nt = 0; nt < 8; nt++) {
            mx0 = fmaxf(mx0, fmaxf(sacc[nt][0], sacc[nt][1]));
            mx1 = fmaxf(mx1, fmaxf(sacc[nt][2], sacc[nt][3]));
        }
        mx0 = fmaxf(mx0, __shfl_xor_sync(0xffffffffu, mx0, 1));
        mx0 = fmaxf(mx0, __shfl_xor_sync(0xffffffffu, mx0, 2));
        mx1 = fmaxf(mx1, __shfl_xor_sync(0xffffffffu, mx1, 1));
        mx1 = fmaxf(mx1, __shfl_xor_sync(0xffffffffu, mx1, 2));
        const float mn0 = fmaxf(m_run0, mx0);
        const float mn1 = fmaxf(m_run1, mx1);
        const float corr0 = __expf(m_run0 - mn0);
        const float corr1 = __expf(m_run1 - mn1);
        m_run0 = mn0; m_run1 = mn1;
        float sum0 = 0.f, sum1 = 0.f;
#pragma unroll
        for (int nt = 0; nt < 8; nt++) {
            sacc[nt][0] = __expf(sacc[nt][0] - mn0);
            sacc[nt][1] = __expf(sacc[nt][1] - mn0);
            sacc[nt][2] = __expf(sacc[nt][2] - mn1);
            sacc[nt][3] = __expf(sacc[nt][3] - mn1);
            sum0 += sacc[nt][0] + sacc[nt][1];
            sum1 += sacc[nt][2] + sacc[nt][3];
        }
        sum0 += __shfl_xor_sync(0xffffffffu, sum0, 1);
        sum0 += __shfl_xor_sync(0xffffffffu, sum0, 2);
        sum1 += __shfl_xor_sync(0xffffffffu, sum1, 1);
        sum1 += __shfl_xor_sync(0xffffffffu, sum1, 2);
        l_run0 = l_run0 * corr0 + sum0;
        l_run1 = l_run1 * corr1 + sum1;
#pragma unroll
        for (int nt = 0; nt < 8; nt++) {
            oacc[nt][0] *= corr0; oacc[nt][1] *= corr0;
            oacc[nt][2] *= corr1; oacc[nt][3] *= corr1;
        }

        uint32_t pa[4][4];
#pragma unroll
        for (int k0 = 0; k0 < 4; k0++) {
            pa[k0][0] = pack_h2(sacc[2 * k0][0], sacc[2 * k0][1]);
            pa[k0][1] = pack_h2(sacc[2 * k0][2], sacc[2 * k0][3]);
            pa[k0][2] = pack_h2(sacc[2 * k0 + 1][0], sacc[2 * k0 + 1][1]);
            pa[k0][3] = pack_h2(sacc[2 * k0 + 1][2], sacc[2 * k0 + 1][3]);
        }

        const uint32_t vbuf = sbase + 2u * (uint32_t)(VH_OFF + cur * KVT);
#pragma unroll
        for (int k0 = 0; k0 < 4; k0++) {
#pragma unroll
            for (int dp = 0; dp < 4; dp++) {
                const uint32_t addr =
                    vbuf + 2 * ((uint32_t)(k0 * 16 * QSH + dp * 16) + vlane);
                uint32_t r0, r1, r2, r3;
                LDMATRIX_X4_TRANS(r0, r1, r2, r3, addr);
                uint32_t b0[2] = {r0, r1};
                uint32_t b1[2] = {r2, r3};
                mma_f16(oacc[2 * dp], pa[k0], b0);
                mma_f16(oacc[2 * dp + 1], pa[k0], b1);
            }
        }
    }

    const float inv0 = 1.f / l_run0;
    const float inv1 = 1.f / l_run1;
    __syncthreads();
#pragma unroll
    for (int nt = 0; nt < 8; nt++) {
        const int d0 = nt * 8 + 2 * tg;
        fs[(it * 64 + d0) * 68 + wq * 16 + g]         = oacc[nt][0] * inv0;
        fs[(it * 64 + d0 + 1) * 68 + wq * 16 + g]     = oacc[nt][1] * inv0;
        fs[(it * 64 + d0) * 68 + wq * 16 + g + 8]     = oacc[nt][2] * inv1;
        fs[(it * 64 + d0 + 1) * 68 + wq * 16 + g + 8] = oacc[nt][3] * inv1;
    }
    __syncthreads();
    {
        const int r = tid >> 1;
        const int half_ = tid & 1;
        const int itr = r >> 6;
        const int d = r & 63;
        __half* dst = O + ((size_t)b * 512 + h * 64 + d) * 512 + i0 + itr * 64 + half_ * 32;
        const float* src = fs + r * 68 + half_ * 32;
#pragma unroll
        for (int u = 0; u < 4; u++) {
            float4 x0 = *(const float4*)&src[u * 8];
            float4 x1 = *(const float4*)&src[u * 8 + 4];
            uint4 pk;
            pk.x = pack_h2(x0.x, x0.y); pk.y = pack_h2(x0.z, x0.w);
            pk.z = pack_h2(x1.x, x1.y); pk.w = pack_h2(x1.z, x1.w);
            *(uint4*)&dst[u * 8] = pk;
        }
    }
}

// ===========================================================================
extern "C" void kernel_launch(void* const* d_in, const int* in_sizes, int n_in,
                              void* d_out, int out_size) {
    (void)in_sizes; (void)n_in; (void)out_size;
    const float* query  = (const float*)d_in[0];
    const float* key    = (const float*)d_in[1];
    const float* value  = (const float*)d_in[2];
    const float* pos    = (const float*)d_in[3];
    const float* proj_w = (const float*)d_in[4];
    const float* proj_b = (const float*)d_in[5];
    const float* q_dw_w = (const float*)d_in[6];
    const float* q_dw_b = (const float*)d_in[7];
    const float* q_pw_w = (const float*)d_in[8];
    const float* q_pw_b = (const float*)d_in[9];
    const float* k_dw_w = (const float*)d_in[10];
    const float* k_dw_b = (const float*)d_in[11];
    const float* k_pw_w = (const float*)d_in[12];
    const float* k_pw_b = (const float*)d_in[13];
    const float* v_dw_w = (const float*)d_in[14];
    const float* v_dw_b = (const float*)d_in[15];
    const float* v_pw_w = (const float*)d_in[16];
    const float* v_pw_b = (const float*)d_in[17];

    __half *tq, *tk, *tv, *q, *k, *v, *o, *whq, *whk, *whv, *whp;
    float *posT;
    cudaGetSymbolAddress((void**)&tq, g_tq);
    cudaGetSymbolAddress((void**)&tk, g_tk);
    cudaGetSymbolAddress((void**)&tv, g_tv);
    cudaGetSymbolAddress((void**)&q, g_q);
    cudaGetSymbolAddress((void**)&k, g_k);
    cudaGetSymbolAddress((void**)&v, g_v);
    cudaGetSymbolAddress((void**)&o, g_o);
    cudaGetSymbolAddress((void**)&whq, g_whq);
    cudaGetSymbolAddress((void**)&whk, g_whk);
    cudaGetSymbolAddress((void**)&whv, g_whv);
    cudaGetSymbolAddress((void**)&whp, g_whp);
    cudaGetSymbolAddress((void**)&posT, g_post);

    cudaFuncSetAttribute(attn_mma_kernel,
                         cudaFuncAttributeMaxDynamicSharedMemorySize, ATTN_SMEM);
    cudaFuncSetAttribute(gemm_mma_kernel<1>,
                         cudaFuncAttributeMaxDynamicSharedMemorySize, GEMM_SMEM);
    cudaFuncSetAttribute(gemm_mma_kernel<0>,
                         cudaFuncAttributeMaxDynamicSharedMemorySize, GEMM_SMEM);

    // prep: pos transpose + weight conversion (one launch)
    prep_kernel<<<768, 256>>>(pos, posT, q_pw_w, k_pw_w, v_pw_w, proj_w,
                              whq, whk, whv, whp);

    // merged q/k/v depthwise conv -> fp16 (b,l,c)
    dwconv_merged_kernel<<<dim3(16, 4, 96), 256>>>(
        query, key, value, posT,
        q_dw_w, k_dw_w, v_dw_w,
        q_dw_b, k_dw_b, v_dw_b,
        tq, tk, tv);

    // merged q/k/v pointwise GEMMs (fp16 out), 128x64 tiles
    gemm_mma_kernel<1><<<dim3(8, 4, 96), 128, GEMM_SMEM>>>(
        tq, tk, tv, whq, whk, whv,
        q_pw_b, k_pw_b, v_pw_b,
        q, k, v);

    // attention -> g_o fp16 (b, c, i)
    attn_mma_kernel<<<dim3(NL / 128, NH, NB), 256, ATTN_SMEM>>>(q, k, v, o);

    // final projection (fp32 out)
    gemm_mma_kernel<0><<<dim3(8, 4, 32), 128, GEMM_SMEM>>>(
        o, o, o, whp, whp, whp, proj_b, proj_b, proj_b,
        d_out, d_out, d_out);
}

// round 17
// speedup vs baseline: 1.1698x; 1.1698x over previous
#include <cuda_runtime.h>
#include <cuda_fp16.h>
#include <cstdint>

#define NB 32
#define NC 512
#define NL 512
#define NH 8
#define NDK 64
#define LC (512 * 512)

// Scratch (device globals). All intermediates fp16.
__device__ __half g_tq[NB * NC * NL];    // dwconv outputs, (b, l, c)
__device__ __half g_tk[NB * NC * NL];
__device__ __half g_tv[NB * NC * NL];
__device__ __half g_q[NB * NC * NL];     // (b, l, c)
__device__ __half g_k[NB * NC * NL];
__device__ __half g_v[NB * NC * NL];
__device__ __half g_o[NB * NC * NL];     // attention output (b, c, i)
__device__ __half g_whq[NC * NC];        // fp16 weights
__device__ __half g_whk[NC * NC];
__device__ __half g_whv[NC * NC];
__device__ __half g_whp[NC * NC];
__device__ float g_post[NC * NL];        // pos_bias transposed to (C, L)

__device__ __forceinline__ uint32_t pack_h2(float lo, float hi) {
    __half2 h = __floats2half2_rn(lo, hi);
    return *(uint32_t*)&h;
}

__device__ __forceinline__ void mma_f16(float* d, const uint32_t* a, const uint32_t* b) {
    asm volatile(
        "mma.sync.aligned.m16n8k16.row.col.f32.f16.f16.f32 "
        "{%0,%1,%2,%3}, {%4,%5,%6,%7}, {%8,%9}, {%0,%1,%2,%3};"
        : "+f"(d[0]), "+f"(d[1]), "+f"(d[2]), "+f"(d[3])
        : "r"(a[0]), "r"(a[1]), "r"(a[2]), "r"(a[3]), "r"(b[0]), "r"(b[1]));
}

#define LDMATRIX_X4(r0, r1, r2, r3, addr) \
    asm volatile("ldmatrix.sync.aligned.m8n8.x4.shared.b16 {%0,%1,%2,%3}, [%4];" \
        : "=r"(r0), "=r"(r1), "=r"(r2), "=r"(r3) : "r"(addr))
#define LDMATRIX_X2(r0, r1, addr) \
    asm volatile("ldmatrix.sync.aligned.m8n8.x2.shared.b16 {%0,%1}, [%2];" \
        : "=r"(r0), "=r"(r1) : "r"(addr))
#define LDMATRIX_X4_TRANS(r0, r1, r2, r3, addr) \
    asm volatile("ldmatrix.sync.aligned.m8n8.x4.trans.shared.b16 {%0,%1,%2,%3}, [%4];" \
        : "=r"(r0), "=r"(r1), "=r"(r2), "=r"(r3) : "r"(addr))

__device__ __forceinline__ uint32_t smem_to_u32(const void* p) {
    uint32_t a;
    asm("{ .reg .u64 t; cvta.to.shared.u64 t, %1; cvt.u32.u64 %0, t; }"
        : "=r"(a) : "l"(p));
    return a;
}

#define CP_ASYNC_16(dst, src) \
    asm volatile("cp.async.cg.shared.global [%0], [%1], 16;" \
        :: "r"(dst), "l"(src) : "memory")
#define CP_COMMIT() asm volatile("cp.async.commit_group;" ::: "memory")
#define CP_WAIT_0() asm volatile("cp.async.wait_group 0;" ::: "memory")
#define CP_WAIT_3() asm volatile("cp.async.wait_group 3;" ::: "memory")

// ===========================================================================
// Prep kernel (ONE launch): blocks 0..255 transpose pos_bias (L,C)->(C,L);
// blocks 256..767 convert the 4 weight matrices fp32->fp16.
// ===========================================================================
__global__ __launch_bounds__(256) void prep_kernel(
    const float* __restrict__ pos, float* __restrict__ posT,
    const float* w0, const float* w1, const float* w2, const float* w3,
    __half* o0, __half* o1, __half* o2, __half* o3) {
    const int bid = blockIdx.x;
    const int tid = threadIdx.x;
    if (bid < 256) {
        __shared__ float tile[32][33];
        const int c0 = (bid & 15) * 32;
        const int l0 = (bid >> 4) * 32;
        const int tx = tid & 31;
        const int ty = tid >> 5;
#pragma unroll
        for (int r = 0; r < 4; r++)
            tile[ty + r * 8][tx] = pos[(size_t)(l0 + ty + r * 8) * NC + c0 + tx];
        __syncthreads();
#pragma unroll
        for (int r = 0; r < 4; r++)
            posT[(size_t)(c0 + ty + r * 8) * NL + l0 + tx] = tile[tx][ty + r * 8];
    } else {
        const int cb = bid - 256;
        const float* ws[4] = {w0, w1, w2, w3};
        __half* os[4] = {o0, o1, o2, o3};
        const float* w = ws[cb >> 7];
        __half* o = os[cb >> 7];
        const int i = ((cb & 127) * 256 + tid) * 8;
        float4 a = *(const float4*)&w[i];
        float4 b = *(const float4*)&w[i + 4];
        uint4 p;
        p.x = pack_h2(a.x, a.y); p.y = pack_h2(a.z, a.w);
        p.z = pack_h2(b.x, b.y); p.w = pack_h2(b.z, b.w);
        *(uint4*)&o[i] = p;
    }
}

// ===========================================================================
// Merged depthwise conv (q,k,v). fp16 output y[iz][b, l, c].
// ===========================================================================
#define DST 137
__global__ __launch_bounds__(256) void dwconv_merged_kernel(
    const float* x0, const float* x1, const float* x2,
    const float* __restrict__ posT,
    const float* w0, const float* w1, const float* w2,
    const float* b0, const float* b1, const float* b2,
    __half* y0, __half* y1, __half* y2) {
    __shared__ float sx[32 * DST];
    const int tid = threadIdx.x;
    const int c0 = blockIdx.x * 32;
    const int l0 = blockIdx.y * 128;
    const int iz = blockIdx.z >> 5;
    const int b = blockIdx.z & 31;
    const float* xin[3] = {x0, x1, x2};
    const float* win3[3] = {w0, w1, w2};
    const float* bin[3] = {b0, b1, b2};
    __half* yout[3] = {y0, y1, y2};
    const float* x = xin[iz];
    const float* w = win3[iz];
    const float* bias = bin[iz];
    __half* y = yout[iz];
    const int add_pos = (iz < 2);

    {
        const int lr = tid >> 3;
        const int tj = tid & 7;
        const float* xrow = x + ((size_t)b * NC + c0 + lr) * NL;
        const float* prow = posT + (size_t)(c0 + lr) * NL;
        float* sd = &sx[lr * DST];
#pragma unroll
        for (int jj = 0; jj < 5; jj++) {
            const int j = tj + jj * 8;
            if (j < 34) {
                const int l = l0 - 4 + 4 * j;
                float4 v = {0.f, 0.f, 0.f, 0.f};
                if (l >= 0 && l <= 508) {
                    v = *(const float4*)&xrow[l];
                    if (add_pos) {
                        float4 p = *(const float4*)&prow[l];
                        v.x += p.x; v.y += p.y; v.z += p.z; v.w += p.w;
                    }
                }
                sd[4 * j + 0] = v.x; sd[4 * j + 1] = v.y;
                sd[4 * j + 2] = v.z; sd[4 * j + 3] = v.w;
            }
        }
    }
    __syncthreads();

    const int cc = tid & 31;
    const int o0 = (tid >> 5) * 16;
    float wt[7];
#pragma unroll
    for (int t = 0; t < 7; t++) wt[t] = w[(c0 + cc) * 7 + t];
    const float bs = bias[c0 + cc];
    const float* xr = &sx[cc * DST];
    float winv[7];
#pragma unroll
    for (int t = 0; t < 6; t++) winv[t] = xr[o0 + 1 + t];
    __half* yb = y + (size_t)b * LC + c0 + cc;
#pragma unroll
    for (int r = 0; r < 16; r++) {
        winv[6] = xr[o0 + r + 7];
        float acc = bs;
#pragma unroll
        for (int t = 0; t < 7; t++) acc += winv[t] * wt[t];
        yb[(size_t)(l0 + o0 + r) * NC] = __float2half_rn(acc);
#pragma unroll
        for (int t = 0; t < 6; t++) winv[t] = winv[t + 1];
    }
}

// ===========================================================================
// PERSISTENT batched GEMM (fp16 m16n8k16, cp.async 5-stage, BK=32):
// Y = A*W^T + bias. Each CTA loops over tiles t += gridDim.x.
// Tile decode: n0=(t&3)*128, m0=((t>>2)&3)*128, z=t>>4 (grp=z>>5, zb=z&31).
// Inner loop identical to R15 (bit-exact accumulation order).
// ===========================================================================
#define PKH2 40
#define GST2 (128 * PKH2)
#define GSTAGES 5
#define GEMM_SMEM (2 * GSTAGES * GST2 * 2)
template <int OUT16>
__global__ __launch_bounds__(256) void gemm_mma_kernel(
    const __half* A0, const __half* A1, const __half* A2,
    const __half* W0, const __half* W1, const __half* W2,
    const float* bi0, const float* bi1, const float* bi2,
    void* Y0, void* Y1, void* Y2, int nTiles) {
    extern __shared__ __align__(16) __half gsm[];
    __half* As = gsm;                       // [GSTAGES][GST2]
    __half* Bs = gsm + GSTAGES * GST2;      // [GSTAGES][GST2]

    const int tid = threadIdx.x;
    const int lane = tid & 31;
    const int g = lane >> 2;
    const int tg = lane & 3;
    const int wm = (tid >> 5) >> 2;
    const int wn = (tid >> 5) & 3;
    const __half* Aarr[3] = {A0, A1, A2};
    const __half* Warr[3] = {W0, W1, W2};
    const float* barr[3] = {bi0, bi1, bi2};
    void* Yarr[3] = {Y0, Y1, Y2};

    const int row = tid >> 1;
    const int hh = tid & 1;
    const uint32_t aSm = smem_to_u32(As);
    const uint32_t bSm = smem_to_u32(Bs);
    const uint32_t aBase = aSm + (uint32_t)(row * PKH2 + hh * 16) * 2;
    const uint32_t bBase = bSm + (uint32_t)(row * PKH2 + hh * 16) * 2;

    const int l15 = lane & 15;
    const uint32_t aln = (uint32_t)(l15 * PKH2 + (lane >> 4) * 8);
    const uint32_t bln = (uint32_t)((l15 & 7) * PKH2 + (l15 >> 3) * 8);

    for (int t = blockIdx.x; t < nTiles; t += gridDim.x) {
        const int n0 = (t & 3) * 128;
        const int m0 = ((t >> 2) & 3) * 128;
        const int zz = t >> 4;
        const int grp = zz >> 5;
        const int zb = zz & 31;
        const __half* Ab = Aarr[grp] + (size_t)zb * LC;
        const __half* W = Warr[grp];
        const float* bias = barr[grp];

        const __half* Asrc = Ab + (size_t)(m0 + row) * 512 + hh * 16;
        const __half* Bsrc = W + (size_t)(n0 + row) * 512 + hh * 16;

        float acc[4][4][4];
#pragma unroll
        for (int mi = 0; mi < 4; mi++)
#pragma unroll
            for (int ni = 0; ni < 4; ni++)
#pragma unroll
                for (int r = 0; r < 4; r++) acc[mi][ni][r] = 0.f;

        // prologue: chunks 0..3 into stages 0..3
#pragma unroll
        for (int pc = 0; pc < 4; pc++) {
            const uint32_t so = (uint32_t)(pc * GST2 * 2);
            CP_ASYNC_16(aBase + so, Asrc + pc * 32);
            CP_ASYNC_16(aBase + so + 16, Asrc + pc * 32 + 8);
            CP_ASYNC_16(bBase + so, Bsrc + pc * 32);
            CP_ASYNC_16(bBase + so + 16, Bsrc + pc * 32 + 8);
            CP_COMMIT();
        }

        for (int kc = 0; kc < 16; kc++) {
            CP_WAIT_3();
            __syncthreads();
            if (kc < 12) {
                const int s = (kc + 4) % GSTAGES;
                const uint32_t so = (uint32_t)(s * GST2 * 2);
                CP_ASYNC_16(aBase + so, Asrc + (kc + 4) * 32);
                CP_ASYNC_16(aBase + so + 16, Asrc + (kc + 4) * 32 + 8);
                CP_ASYNC_16(bBase + so, Bsrc + (kc + 4) * 32);
                CP_ASYNC_16(bBase + so + 16, Bsrc + (kc + 4) * 32 + 8);
            }
            CP_COMMIT();

            const int cur = kc % GSTAGES;
            const uint32_t aCur = aSm + (uint32_t)(cur * GST2) * 2;
            const uint32_t bCur = bSm + (uint32_t)(cur * GST2) * 2;
#pragma unroll
            for (int s = 0; s < 2; s++) {
                uint32_t af[4][4];
#pragma unroll
                for (int mi = 0; mi < 4; mi++) {
                    const uint32_t addr = aCur +
                        2u * (uint32_t)((wm * 64 + mi * 16) * PKH2 + s * 16 + aln);
                    LDMATRIX_X4(af[mi][0], af[mi][1], af[mi][2], af[mi][3], addr);
                }
                uint32_t bf[4][2];
#pragma unroll
                for (int ni = 0; ni < 4; ni++) {
                    const uint32_t addr = bCur +
                        2u * (uint32_t)((wn * 32 + ni * 8) * PKH2 + s * 16 + bln);
                    LDMATRIX_X2(bf[ni][0], bf[ni][1], addr);
                }
#pragma unroll
                for (int mi = 0; mi < 4; mi++)
#pragma unroll
                    for (int ni = 0; ni < 4; ni++)
                        mma_f16(acc[mi][ni], af[mi], bf[ni]);
            }
        }

#pragma unroll
        for (int mi = 0; mi < 4; mi++) {
            const int m = m0 + wm * 64 + mi * 16 + g;
#pragma unroll
            for (int ni = 0; ni < 4; ni++) {
                const int n = n0 + wn * 32 + ni * 8 + 2 * tg;
                const float bn0 = bias[n], bn1 = bias[n + 1];
                if (OUT16) {
                    __half* Yb = (__half*)Yarr[grp] + (size_t)zb * LC;
                    *(uint32_t*)&Yb[(size_t)m * 512 + n] =
                        pack_h2(acc[mi][ni][0] + bn0, acc[mi][ni][1] + bn1);
                    *(uint32_t*)&Yb[(size_t)(m + 8) * 512 + n] =
                        pack_h2(acc[mi][ni][2] + bn0, acc[mi][ni][3] + bn1);
                } else {
                    float* Yb = (float*)Yarr[grp] + (size_t)zb * LC;
                    float2 o0 = {acc[mi][ni][0] + bn0, acc[mi][ni][1] + bn1};
                    float2 o1 = {acc[mi][ni][2] + bn0, acc[mi][ni][3] + bn1};
                    *(float2*)&Yb[(size_t)m * 512 + n] = o0;
                    *(float2*)&Yb[(size_t)(m + 8) * 512 + n] = o1;
                }
            }
        }
        __syncthreads();  // all reads of smem stages done before next tile's prologue
    }
}

// ===========================================================================
// Flash attention (fp16 m16n8k16), 128-i CTA, 256 thr = 8 warps.
// [R15 proven-best config — unchanged]
// ===========================================================================
#define QSH 72
#define KH_OFF (128 * QSH)
#define VH_OFF (KH_OFF + 2 * 64 * QSH)
#define KVT (64 * QSH)
#define ATTN_SMEM ((VH_OFF + 2 * 64 * QSH) * 2)
__global__ __launch_bounds__(256) void attn_mma_kernel(
    const __half* __restrict__ Q, const __half* __restrict__ K,
    const __half* __restrict__ V, __half* __restrict__ O) {
    extern __shared__ __align__(16) char smc[];
    __half* sh = (__half*)smc;
    float* fs = (float*)smc;
    const uint32_t sbase = smem_to_u32(smc);

    const int tid = threadIdx.x;
    const int w = tid >> 5;
    const int lane = tid & 31;
    const int g = lane >> 2;
    const int tg = lane & 3;
    const int it = w >> 2;
    const int wq = w & 3;
    const int b = blockIdx.z;
    const int h = blockIdx.y;
    const int i0 = blockIdx.x * 128;

    const __half* Qb = Q + (size_t)b * LC + h * 64;
    const __half* Kb = K + (size_t)b * LC + h * 64;
    const __half* Vb = V + (size_t)b * LC + h * 64;

    const int krow = tid >> 2;
    const int kq = tid & 3;
    const __half* Ksrc = Kb + (size_t)krow * 512 + kq * 16;
    const __half* Vsrc = Vb + (size_t)krow * 512 + kq * 16;
    const uint32_t kBase = sbase + (uint32_t)(KH_OFF + krow * QSH + kq * 16) * 2;
    const uint32_t vBase = sbase + (uint32_t)(VH_OFF + krow * QSH + kq * 16) * 2;

    CP_ASYNC_16(kBase, Ksrc);
    CP_ASYNC_16(kBase + 16, Ksrc + 8);
    CP_ASYNC_16(vBase, Vsrc);
    CP_ASYNC_16(vBase + 16, Vsrc + 8);
    CP_COMMIT();

    {
        const __half2 sc = __half2half2(__float2half_rn(0.125f));
        const int row = tid >> 1;
        const int half_ = tid & 1;
        const __half* src = Qb + (size_t)(i0 + row) * 512 + half_ * 32;
        __half* qd = sh + row * QSH + half_ * 32;
#pragma unroll
        for (int u = 0; u < 4; u++) {
            uint4 v = *(const uint4*)&src[u * 8];
            __half2* h2 = (__half2*)&v;
            h2[0] = __hmul2(h2[0], sc);
            h2[1] = __hmul2(h2[1], sc);
            h2[2] = __hmul2(h2[2], sc);
            h2[3] = __hmul2(h2[3], sc);
            *(uint4*)&qd[u * 8] = v;
        }
    }
    __syncthreads();

    uint32_t qa[4][4];
    {
        const __half* qrow = sh + (it * 64 + wq * 16 + g) * QSH + 2 * tg;
#pragma unroll
        for (int k0 = 0; k0 < 4; k0++) {
            const __half* qp = qrow + k0 * 16;
            qa[k0][0] = *(const uint32_t*)&qp[0];
            qa[k0][1] = *(const uint32_t*)&qp[8 * QSH];
            qa[k0][2] = *(const uint32_t*)&qp[8];
            qa[k0][3] = *(const uint32_t*)&qp[8 * QSH + 8];
        }
    }

    float m_run0 = -1e30f, m_run1 = -1e30f, l_run0 = 0.f, l_run1 = 0.f;
    float oacc[8][4];
#pragma unroll
    for (int nt = 0; nt < 8; nt++)
#pragma unroll
        for (int r = 0; r < 4; r++) oacc[nt][r] = 0.f;

    const uint32_t vlane = (uint32_t)(((lane & 7) + ((lane >> 3) & 1) * 8) * QSH
                                      + ((lane >> 4) & 1) * 8);
    const int l15 = lane & 15;
    const uint32_t kln = (uint32_t)((l15 & 7) * QSH + (l15 >> 3) * 8 + (lane >> 4) * 16);

    for (int jt = 0; jt < 8; jt++) {
        const int cur = jt & 1;
        CP_WAIT_0();
        __syncthreads();
        if (jt < 7) {
            const int nxt = (jt + 1) & 1;
            const __half* ks = Ksrc + (size_t)(jt + 1) * 64 * 512;
            const __half* vs = Vsrc + (size_t)(jt + 1) * 64 * 512;
            CP_ASYNC_16(kBase + (uint32_t)(nxt * KVT) * 2, ks);
            CP_ASYNC_16(kBase + (uint32_t)(nxt * KVT) * 2 + 16, ks + 8);
            CP_ASYNC_16(vBase + (uint32_t)(nxt * KVT) * 2, vs);
            CP_ASYNC_16(vBase + (uint32_t)(nxt * KVT) * 2 + 16, vs + 8);
        }
        CP_COMMIT();

        const uint32_t kTile = sbase + 2u * (uint32_t)(KH_OFF + cur * KVT);

        float sacc[8][4];
#pragma unroll
        for (int nt = 0; nt < 8; nt++)
#pragma unroll
            for (int r = 0; r < 4; r++) sacc[nt][r] = 0.f;
#pragma unroll
        for (int p = 0; p < 2; p++) {
#pragma unroll
            for (int nt = 0; nt < 8; nt++) {
                const uint32_t addr = kTile +
                    2u * (uint32_t)((nt * 8) * QSH + p * 32 + kln);
                uint32_t r0, r1, r2, r3;
                LDMATRIX_X4(r0, r1, r2, r3, addr);
                uint32_t b0[2] = {r0, r1};
                uint32_t b1[2] = {r2, r3};
                mma_f16(sacc[nt], qa[2 * p], b0);
                mma_f16(sacc[nt], qa[2 * p + 1], b1);
            }
        }

        float mx0 = -1e30f, mx1 = -1e30f;
#pragma unroll
        for (int nt = 0; nt < 8; nt++) {
            mx0 = fmaxf(mx0, fmaxf(sacc[nt][0], sacc[nt][1]));
            mx1 = fmaxf(mx1, fmaxf(sacc[nt][2], sacc[nt][3]));
        }
        mx0 = fmaxf(mx0, __shfl_xor_sync(0xffffffffu, mx0, 1));
        mx0 = fmaxf(mx0, __shfl_xor_sync(0xffffffffu, mx0, 2));
        mx1 = fmaxf(mx1, __shfl_xor_sync(0xffffffffu, mx1, 1));
        mx1 = fmaxf(mx1, __shfl_xor_sync(0xffffffffu, mx1, 2));
        const float mn0 = fmaxf(m_run0, mx0);
        const float mn1 = fmaxf(m_run1, mx1);
        const float corr0 = __expf(m_run0 - mn0);
        const float corr1 = __expf(m_run1 - mn1);
        m_run0 = mn0; m_run1 = mn1;
        float sum0 = 0.f, sum1 = 0.f;
#pragma unroll
        for (int nt = 0; nt < 8; nt++) {
            sacc[nt][0] = __expf(sacc[nt][0] - mn0);
            sacc[nt][1] = __expf(sacc[nt][1] - mn0);
            sacc[nt][2] = __expf(sacc[nt][2] - mn1);
            sacc[nt][3] = __expf(sacc[nt][3] - mn1);
            sum0 += sacc[nt][0] + sacc[nt][1];
            sum1 += sacc[nt][2] + sacc[nt][3];
        }
        sum0 += __shfl_xor_sync(0xffffffffu, sum0, 1);
        sum0 += __shfl_xor_sync(0xffffffffu, sum0, 2);
        sum1 += __shfl_xor_sync(0xffffffffu, sum1, 1);
        sum1 += __shfl_xor_sync(0xffffffffu, sum1, 2);
        l_run0 = l_run0 * corr0 + sum0;
        l_run1 = l_run1 * corr1 + sum1;
#pragma unroll
        for (int nt = 0; nt < 8; nt++) {
            oacc[nt][0] *= corr0; oacc[nt][1] *= corr0;
            oacc[nt][2] *= corr1; oacc[nt][3] *= corr1;
        }

        uint32_t pa[4][4];
#pragma unroll
        for (int k0 = 0; k0 < 4; k0++) {
            pa[k0][0] = pack_h2(sacc[2 * k0][0], sacc[2 * k0][1]);
            pa[k0][1] = pack_h2(sacc[2 * k0][2], sacc[2 * k0][3]);
            pa[k0][2] = pack_h2(sacc[2 * k0 + 1][0], sacc[2 * k0 + 1][1]);
            pa[k0][3] = pack_h2(sacc[2 * k0 + 1][2], sacc[2 * k0 + 1][3]);
        }

        const uint32_t vbuf = sbase + 2u * (uint32_t)(VH_OFF + cur * KVT);
#pragma unroll
        for (int k0 = 0; k0 < 4; k0++) {
#pragma unroll
            for (int dp = 0; dp < 4; dp++) {
                const uint32_t addr =
                    vbuf + 2 * ((uint32_t)(k0 * 16 * QSH + dp * 16) + vlane);
                uint32_t r0, r1, r2, r3;
                LDMATRIX_X4_TRANS(r0, r1, r2, r3, addr);
                uint32_t b0[2] = {r0, r1};
                uint32_t b1[2] = {r2, r3};
                mma_f16(oacc[2 * dp], pa[k0], b0);
                mma_f16(oacc[2 * dp + 1], pa[k0], b1);
            }
        }
    }

    const float inv0 = 1.f / l_run0;
    const float inv1 = 1.f / l_run1;
    __syncthreads();
#pragma unroll
    for (int nt = 0; nt < 8; nt++) {
        const int d0 = nt * 8 + 2 * tg;
        fs[(it * 64 + d0) * 68 + wq * 16 + g]         = oacc[nt][0] * inv0;
        fs[(it * 64 + d0 + 1) * 68 + wq * 16 + g]     = oacc[nt][1] * inv0;
        fs[(it * 64 + d0) * 68 + wq * 16 + g + 8]     = oacc[nt][2] * inv1;
        fs[(it * 64 + d0 + 1) * 68 + wq * 16 + g + 8] = oacc[nt][3] * inv1;
    }
    __syncthreads();
    {
        const int r = tid >> 1;
        const int half_ = tid & 1;
        const int itr = r >> 6;
        const int d = r & 63;
        __half* dst = O + ((size_t)b * 512 + h * 64 + d) * 512 + i0 + itr * 64 + half_ * 32;
        const float* src = fs + r * 68 + half_ * 32;
#pragma unroll
        for (int u = 0; u < 4; u++) {
            float4 x0 = *(const float4*)&src[u * 8];
            float4 x1 = *(const float4*)&src[u * 8 + 4];
            uint4 pk;
            pk.x = pack_h2(x0.x, x0.y); pk.y = pack_h2(x0.z, x0.w);
            pk.z = pack_h2(x1.x, x1.y); pk.w = pack_h2(x1.z, x1.w);
            *(uint4*)&dst[u * 8] = pk;
        }
    }
}

// ===========================================================================
extern "C" void kernel_launch(void* const* d_in, const int* in_sizes, int n_in,
                              void* d_out, int out_size) {
    (void)in_sizes; (void)n_in; (void)out_size;
    const float* query  = (const float*)d_in[0];
    const float* key    = (const float*)d_in[1];
    const float* value  = (const float*)d_in[2];
    const float* pos    = (const float*)d_in[3];
    const float* proj_w = (const float*)d_in[4];
    const float* proj_b = (const float*)d_in[5];
    const float* q_dw_w = (const float*)d_in[6];
    const float* q_dw_b = (const float*)d_in[7];
    const float* q_pw_w = (const float*)d_in[8];
    const float* q_pw_b = (const float*)d_in[9];
    const float* k_dw_w = (const float*)d_in[10];
    const float* k_dw_b = (const float*)d_in[11];
    const float* k_pw_w = (const float*)d_in[12];
    const float* k_pw_b = (const float*)d_in[13];
    const float* v_dw_w = (const float*)d_in[14];
    const float* v_dw_b = (const float*)d_in[15];
    const float* v_pw_w = (const float*)d_in[16];
    const float* v_pw_b = (const float*)d_in[17];

    __half *tq, *tk, *tv, *q, *k, *v, *o, *whq, *whk, *whv, *whp;
    float *posT;
    cudaGetSymbolAddress((void**)&tq, g_tq);
    cudaGetSymbolAddress((void**)&tk, g_tk);
    cudaGetSymbolAddress((void**)&tv, g_tv);
    cudaGetSymbolAddress((void**)&q, g_q);
    cudaGetSymbolAddress((void**)&k, g_k);
    cudaGetSymbolAddress((void**)&v, g_v);
    cudaGetSymbolAddress((void**)&o, g_o);
    cudaGetSymbolAddress((void**)&whq, g_whq);
    cudaGetSymbolAddress((void**)&whk, g_whk);
    cudaGetSymbolAddress((void**)&whv, g_whv);
    cudaGetSymbolAddress((void**)&whp, g_whp);
    cudaGetSymbolAddress((void**)&posT, g_post);

    cudaFuncSetAttribute(attn_mma_kernel,
                         cudaFuncAttributeMaxDynamicSharedMemorySize, ATTN_SMEM);
    cudaFuncSetAttribute(gemm_mma_kernel<1>,
                         cudaFuncAttributeMaxDynamicSharedMemorySize, GEMM_SMEM);
    cudaFuncSetAttribute(gemm_mma_kernel<0>,
                         cudaFuncAttributeMaxDynamicSharedMemorySize, GEMM_SMEM);

    // prep: pos transpose + weight conversion (one launch)
    prep_kernel<<<768, 256>>>(pos, posT, q_pw_w, k_pw_w, v_pw_w, proj_w,
                              whq, whk, whv, whp);

    // merged q/k/v depthwise conv -> fp16 (b,l,c)
    dwconv_merged_kernel<<<dim3(16, 4, 96), 256>>>(
        query, key, value, posT,
        q_dw_w, k_dw_w, v_dw_w,
        q_dw_b, k_dw_b, v_dw_b,
        tq, tk, tv);

    // merged q/k/v pointwise GEMMs (fp16 out), persistent CTAs (2/SM x 152 SMs)
    gemm_mma_kernel<1><<<304, 256, GEMM_SMEM>>>(
        tq, tk, tv, whq, whk, whv,
        q_pw_b, k_pw_b, v_pw_b,
        q, k, v, 1536);

    // attention -> g_o fp16 (b, c, i)
    attn_mma_kernel<<<dim3(NL / 128, NH, NB), 256, ATTN_SMEM>>>(q, k, v, o);

    // final projection (fp32 out), persistent
    gemm_mma_kernel<0><<<304, 256, GEMM_SMEM>>>(
        o, o, o, whp, whp, whp, proj_b, proj_b, proj_b,
        d_out, d_out, d_out, 512);
}